// round 2
// baseline (speedup 1.0000x reference)
#include <cuda_runtime.h>

// ASTGC_37976100831379
//
// Dead-graph analysis: the reference returns fusion_out[:, 0], i.e. the star-
// graph hub node, which receives NO messages (row 0 of the concat is an
// explicit zeros tensor). Therefore:
//
//     out[b, s, 0] = fgcn_b[s]        for all b in [0,32), s in [0,48)
//
// Everything else in the reference (both TCN branches, the O(B*N^2) GCN edge
// aggregation, fusion GEMMs, cross-batch softmax attention) is dead code with
// respect to the output. The optimal kernel is a 48-float -> 1536-float
// broadcast.

#define ASTGC_B 32
#define ASTGC_S 48

__global__ void astgc_bias_broadcast_kernel(const float* __restrict__ fgcn_b,
                                            float* __restrict__ out,
                                            int total) {
    int i = blockIdx.x * blockDim.x + threadIdx.x;
    if (i < total) {
        // out is [B, S, 1] row-major: flat index i -> s = i % S
        out[i] = fgcn_b[i % ASTGC_S];
    }
}

extern "C" void kernel_launch(void* const* d_in, const int* in_sizes, int n_in,
                              void* d_out, int out_size) {
    // Locate fgcn_b: the unique input with exactly S=48 elements.
    // (All other bias vectors are 64 elements or 1; fgcn_w is 64*48=3072.)
    int bias_idx = -1;
    for (int i = 0; i < n_in; ++i) {
        if (in_sizes[i] == ASTGC_S) { bias_idx = i; break; }
    }
    if (bias_idx < 0) bias_idx = 30;  // setup_inputs order fallback: fgcn_b is input #30

    const float* fgcn_b = (const float*)d_in[bias_idx];
    float* out = (float*)d_out;

    const int total = out_size;  // B*S = 1536
    const int threads = 256;
    const int blocks = (total + threads - 1) / threads;
    astgc_bias_broadcast_kernel<<<blocks, threads>>>(fgcn_b, out, total);
}